// round 1
// baseline (speedup 1.0000x reference)
#include <cuda_runtime.h>

#define NB 8
#define NS 1024
#define ND 128
#define NBS (NB*NS)   // 8192

// scratch (static __device__ allocations only, per harness rules)
__device__ float g_K[NBS*ND];
__device__ float g_V[NBS*ND];
__device__ float g_Q[NBS*ND];
__device__ float g_G[NBS*3];
__device__ float g_Err[NBS*ND];
__device__ float g_cM[NBS];
__device__ float g_cS[NBS];
__device__ int   g_flags[NB*32];

// ---------------------------------------------------------------------------
// Kernel 1: projections K = x@Wk, V = x@Wv, Q = x@Wq
// grid (128 row-tiles, 3 matrices), 256 threads. 64 rows x 128 cols per block.
// ---------------------------------------------------------------------------
__global__ void proj_kernel(const float* __restrict__ x,
                            const float* __restrict__ Wk,
                            const float* __restrict__ Wv,
                            const float* __restrict__ Wq) {
    __shared__ float4 xs[64][32];
    const int tile = blockIdx.x;
    const int mat  = blockIdx.y;
    const float* W = (mat == 0) ? Wk : (mat == 1) ? Wv : Wq;
    float* out     = (mat == 0) ? g_K : (mat == 1) ? g_V : g_Q;
    const int tid = threadIdx.x;

    const float4* x4 = (const float4*)(x + (size_t)tile * 64 * ND);
#pragma unroll
    for (int j = 0; j < 8; j++) {
        int idx = tid + j * 256;        // 2048 float4s
        xs[idx >> 5][idx & 31] = x4[idx];
    }
    __syncthreads();

    const int c0 = (tid & 31) * 4;      // col base
    const int rb = (tid >> 5) * 8;      // row base
    float acc[8][4];
#pragma unroll
    for (int r = 0; r < 8; r++)
#pragma unroll
        for (int c = 0; c < 4; c++) acc[r][c] = 0.f;

    for (int k4 = 0; k4 < 32; k4++) {
        float wk[4][4];
#pragma unroll
        for (int kk = 0; kk < 4; kk++) {
            float4 w = *(const float4*)(W + (k4 * 4 + kk) * ND + c0);
            wk[kk][0] = w.x; wk[kk][1] = w.y; wk[kk][2] = w.z; wk[kk][3] = w.w;
        }
#pragma unroll
        for (int r = 0; r < 8; r++) {
            float4 xv = xs[rb + r][k4];
            float xr[4] = {xv.x, xv.y, xv.z, xv.w};
#pragma unroll
            for (int kk = 0; kk < 4; kk++)
#pragma unroll
                for (int c = 0; c < 4; c++)
                    acc[r][c] = fmaf(xr[kk], wk[kk][c], acc[r][c]);
        }
    }
#pragma unroll
    for (int r = 0; r < 8; r++) {
        float4 res = make_float4(acc[r][0], acc[r][1], acc[r][2], acc[r][3]);
        *(float4*)(out + (size_t)(tile * 64 + rb + r) * ND + c0) = res;
    }
}

// ---------------------------------------------------------------------------
// Kernel 2: gates = sigmoid(x @ Wg + bg), one warp per row
// ---------------------------------------------------------------------------
__global__ void gates_kernel(const float* __restrict__ x,
                             const float* __restrict__ Wg,
                             const float* __restrict__ bg) {
    int gwarp = (blockIdx.x * blockDim.x + threadIdx.x) >> 5;
    int lane  = threadIdx.x & 31;
    if (gwarp >= NBS) return;
    float4 xv = ((const float4*)x)[gwarp * 32 + lane];
    float xr[4] = {xv.x, xv.y, xv.z, xv.w};
    float d0 = 0.f, d1 = 0.f, d2 = 0.f;
    int kb = lane * 4;
#pragma unroll
    for (int j = 0; j < 4; j++) {
        const float* wr = Wg + (kb + j) * 3;
        d0 = fmaf(xr[j], wr[0], d0);
        d1 = fmaf(xr[j], wr[1], d1);
        d2 = fmaf(xr[j], wr[2], d2);
    }
#pragma unroll
    for (int off = 16; off; off >>= 1) {
        d0 += __shfl_xor_sync(0xffffffffu, d0, off);
        d1 += __shfl_xor_sync(0xffffffffu, d1, off);
        d2 += __shfl_xor_sync(0xffffffffu, d2, off);
    }
    if (lane == 0) {
        g_G[gwarp * 3 + 0] = 1.f / (1.f + expf(-(d0 + bg[0])));
        g_G[gwarp * 3 + 1] = 1.f / (1.f + expf(-(d1 + bg[1])));
        g_G[gwarp * 3 + 2] = 1.f / (1.f + expf(-(d2 + bg[2])));
    }
}

// ---------------------------------------------------------------------------
// Kernel 3: grid 16. Blocks 0..7: forward diagonal scan (y, err).
//           Blocks 8..15: backward suffix scans -> cM, cS + activity flags.
// ---------------------------------------------------------------------------
__global__ void scan_kernel(float* __restrict__ y_out) {
    const int bid = blockIdx.x;
    if (bid < NB) {
        // ---------------- forward scan: one thread per d ----------------
        const int b = bid, d = threadIdx.x;
        const size_t base = (size_t)b * NS * ND + d;
        const float* __restrict__ Kp = g_K + base;
        const float* __restrict__ Vp = g_V + base;
        const float* __restrict__ Qp = g_Q + base;
        float* __restrict__ Ep = g_Err + base;
        float* __restrict__ Yp = y_out + base;
        const float* __restrict__ gp = g_G + (size_t)b * NS * 3;

        float m = 0.f, s = 0.f;
#pragma unroll 4
        for (int t = 0; t < NS; t++) {
            const int off = t * ND;
            float k = Kp[off], v = Vp[off], q = Qp[off];
            float a  = gp[t * 3 + 0];
            float e  = gp[t * 3 + 1];
            float th = gp[t * 3 + 2];
            Yp[off] = q * m;
            float err = fmaf(k, m, -v);
            Ep[off] = err;
            s = fmaf(e, s, -th * (k * err));
            m = fmaf(1.f - a, m, s);
        }
    } else {
        // ------------- backward scalar scans: cS_r = -th_r * E_r,
        //               cM_r = -th_r * W_r,  W_r = A_r + e_{r+1} W_{r+1} ----
        const int b = bid - NB;
        const int i = threadIdx.x;          // 0..127, chunk of 8 timesteps
        const int lo = i * 8;
        const float* __restrict__ gb = g_G + (size_t)b * NS * 3;

        float ev[8], av[8], thv[8];
#pragma unroll
        for (int j = 0; j < 8; j++) {
            av[j]  = 1.f - gb[(lo + j) * 3 + 0];
            ev[j]  = gb[(lo + j) * 3 + 1];
            thv[j] = gb[(lo + j) * 3 + 2];
        }
        float e_next = (lo + 8 < NS) ? gb[(lo + 8) * 3 + 1] : 0.f;

        __shared__ float sLe[128], sLa[128], sAa[128], sBa[128];
        __shared__ float sTe[128], sTa[128], sTw[128];

        float Le = 1.f, La = 1.f;
#pragma unroll
        for (int j = 0; j < 8; j++) { Le *= ev[j]; La *= av[j]; }
        sLe[i] = Le; sLa[i] = La;
        __syncthreads();
        if (i == 0) {       // exclusive suffix products across chunks
            float te = 1.f, ta = 1.f;
            for (int c = 127; c >= 0; c--) {
                sTe[c] = te; sTa[c] = ta;
                te *= sLe[c]; ta *= sLa[c];
            }
        }
        __syncthreads();

        float E[8], A[8];
        {
            float re = sTe[i], ra = sTa[i];
#pragma unroll
            for (int j = 7; j >= 0; j--) {
                E[j] = re; A[j] = ra;
                re *= ev[j]; ra *= av[j];
            }
        }
        // local affine composition for W (map: W_tail -> W_{lo})
        float Aa = 1.f, Ba = 0.f;
#pragma unroll
        for (int j = 7; j >= 0; j--) {
            float al = (j == 7) ? e_next : ev[j + 1];
            Aa = al * Aa;
            Ba = fmaf(al, Ba, A[j]);
        }
        sAa[i] = Aa; sBa[i] = Ba;
        __syncthreads();
        if (i == 0) {       // tail W per chunk (value of W at hi(c)+1)
            float w = 0.f;
            for (int c = 127; c >= 0; c--) {
                sTw[c] = w;
                w = fmaf(sAa[c], w, sBa[c]);
            }
        }
        __syncthreads();

        float w = sTw[i];
        int flag = 0;
#pragma unroll
        for (int j = 7; j >= 0; j--) {
            float al = (j == 7) ? e_next : ev[j + 1];
            w = fmaf(al, w, A[j]);                  // = W_{lo+j}
            float cm = -thv[j] * w;
            float cs = -thv[j] * E[j];
            g_cM[b * NS + lo + j] = cm;
            g_cS[b * NS + lo + j] = cs;
            if (fabsf(cm) > 1e-18f || fabsf(cs) > 1e-18f) flag = 1;
        }
        if (flag) atomicOr(&g_flags[b * 32 + (i >> 2)], 1);
    }
}

// ---------------------------------------------------------------------------
// Kernel 4: M_final/S_final = (c o K)^T @ Err  (per batch), split-K=32 with
// activity-flag skip, atomicAdd accumulate into zeroed d_out region.
// grid (32 splits, 2 which, 8 b), 256 threads.
// ---------------------------------------------------------------------------
__global__ void final_kernel(float* __restrict__ out) {
    const int split = blockIdx.x;
    const int which = blockIdx.y;   // 0 -> M (cM), 1 -> S (cS)
    const int b = blockIdx.z;
    if (!g_flags[b * 32 + split]) return;

    __shared__ float As[32][128];
    __shared__ float Bs[32][128];
    const float* __restrict__ cw = which ? g_cS : g_cM;
    const int t0 = split * 32;
    const int tid = threadIdx.x;

    for (int idx = tid; idx < 32 * 128; idx += 256) {
        int kk = idx >> 7, col = idx & 127;
        size_t t = (size_t)b * NS + t0 + kk;
        float cv = cw[t];
        As[kk][col] = cv * g_K[t * ND + col];
        Bs[kk][col] = g_Err[t * ND + col];
    }
    __syncthreads();

    const int tx = tid & 15, ty = tid >> 4;
    const int i0 = ty * 8, j0 = tx * 8;
    float acc[8][8];
#pragma unroll
    for (int r = 0; r < 8; r++)
#pragma unroll
        for (int c = 0; c < 8; c++) acc[r][c] = 0.f;

    for (int kk = 0; kk < 32; kk++) {
        float avv[8], bvv[8];
        float4 a0 = *(const float4*)&As[kk][i0];
        float4 a1 = *(const float4*)&As[kk][i0 + 4];
        float4 b0 = *(const float4*)&Bs[kk][j0];
        float4 b1 = *(const float4*)&Bs[kk][j0 + 4];
        avv[0]=a0.x; avv[1]=a0.y; avv[2]=a0.z; avv[3]=a0.w;
        avv[4]=a1.x; avv[5]=a1.y; avv[6]=a1.z; avv[7]=a1.w;
        bvv[0]=b0.x; bvv[1]=b0.y; bvv[2]=b0.z; bvv[3]=b0.w;
        bvv[4]=b1.x; bvv[5]=b1.y; bvv[6]=b1.z; bvv[7]=b1.w;
#pragma unroll
        for (int r = 0; r < 8; r++)
#pragma unroll
            for (int c = 0; c < 8; c++)
                acc[r][c] = fmaf(avv[r], bvv[c], acc[r][c]);
    }

    float* o = out + (size_t)NBS * ND + (size_t)which * NB * ND * ND
                 + (size_t)b * ND * ND;
#pragma unroll
    for (int r = 0; r < 8; r++)
#pragma unroll
        for (int c = 0; c < 8; c++)
            atomicAdd(&o[(i0 + r) * ND + j0 + c], acc[r][c]);
}

// ---------------------------------------------------------------------------
extern "C" void kernel_launch(void* const* d_in, const int* in_sizes, int n_in,
                              void* d_out, int out_size) {
    const float* x  = (const float*)d_in[0];
    const float* Wk = (const float*)d_in[1];
    const float* Wv = (const float*)d_in[2];
    const float* Wq = (const float*)d_in[3];
    const float* Wg = (const float*)d_in[4];
    const float* bg = (const float*)d_in[5];
    float* out = (float*)d_out;

    void* flagsPtr = nullptr;
    cudaGetSymbolAddress(&flagsPtr, g_flags);
    cudaMemsetAsync(flagsPtr, 0, sizeof(int) * NB * 32);
    // zero the M_final / S_final region (outputs region fully overwritten)
    cudaMemsetAsync(out + (size_t)NBS * ND, 0,
                    (size_t)2 * NB * ND * ND * sizeof(float));

    proj_kernel<<<dim3(128, 3), 256>>>(x, Wk, Wv, Wq);
    gates_kernel<<<1024, 256>>>(x, Wg, bg);
    scan_kernel<<<16, 128>>>(out);
    final_kernel<<<dim3(32, 2, 8), 256>>>(out);
}

// round 2
// speedup vs baseline: 4.5971x; 4.5971x over previous
#include <cuda_runtime.h>

#define NB 8
#define NS 1024
#define ND 128
#define NBS (NB*NS)   // 8192

// scratch (static __device__ allocations only, per harness rules)
__device__ float g_K[NBS*ND];
__device__ float g_V[NBS*ND];
__device__ float g_Q[NBS*ND];
__device__ float g_G[NBS*3];
__device__ float g_Err[NBS*ND];
__device__ float g_cM[NBS];
__device__ float g_cS[NBS];
__device__ int   g_tstart[NB];

// ---------------------------------------------------------------------------
// Kernel 1: projections K = x@Wk, V = x@Wv, Q = x@Wq
// grid (128 row-tiles, 3 matrices), 256 threads. 64 rows x 128 cols per block.
// ---------------------------------------------------------------------------
__global__ void proj_kernel(const float* __restrict__ x,
                            const float* __restrict__ Wk,
                            const float* __restrict__ Wv,
                            const float* __restrict__ Wq) {
    __shared__ float4 xs[64][32];
    const int tile = blockIdx.x;
    const int mat  = blockIdx.y;
    const float* W = (mat == 0) ? Wk : (mat == 1) ? Wv : Wq;
    float* out     = (mat == 0) ? g_K : (mat == 1) ? g_V : g_Q;
    const int tid = threadIdx.x;

    const float4* x4 = (const float4*)(x + (size_t)tile * 64 * ND);
#pragma unroll
    for (int j = 0; j < 8; j++) {
        int idx = tid + j * 256;        // 2048 float4s
        xs[idx >> 5][idx & 31] = x4[idx];
    }
    __syncthreads();

    const int c0 = (tid & 31) * 4;      // col base
    const int rb = (tid >> 5) * 8;      // row base
    float acc[8][4];
#pragma unroll
    for (int r = 0; r < 8; r++)
#pragma unroll
        for (int c = 0; c < 4; c++) acc[r][c] = 0.f;

    for (int k4 = 0; k4 < 32; k4++) {
        float wk[4][4];
#pragma unroll
        for (int kk = 0; kk < 4; kk++) {
            float4 w = *(const float4*)(W + (k4 * 4 + kk) * ND + c0);
            wk[kk][0] = w.x; wk[kk][1] = w.y; wk[kk][2] = w.z; wk[kk][3] = w.w;
        }
#pragma unroll
        for (int r = 0; r < 8; r++) {
            float4 xv = xs[rb + r][k4];
            float xr[4] = {xv.x, xv.y, xv.z, xv.w};
#pragma unroll
            for (int kk = 0; kk < 4; kk++)
#pragma unroll
                for (int c = 0; c < 4; c++)
                    acc[r][c] = fmaf(xr[kk], wk[kk][c], acc[r][c]);
        }
    }
#pragma unroll
    for (int r = 0; r < 8; r++) {
        float4 res = make_float4(acc[r][0], acc[r][1], acc[r][2], acc[r][3]);
        *(float4*)(out + (size_t)(tile * 64 + rb + r) * ND + c0) = res;
    }
}

// ---------------------------------------------------------------------------
// Kernel 2: gates = sigmoid(x @ Wg + bg), one warp per row
// ---------------------------------------------------------------------------
__global__ void gates_kernel(const float* __restrict__ x,
                             const float* __restrict__ Wg,
                             const float* __restrict__ bg) {
    int gwarp = (blockIdx.x * blockDim.x + threadIdx.x) >> 5;
    int lane  = threadIdx.x & 31;
    if (gwarp >= NBS) return;
    float4 xv = ((const float4*)x)[gwarp * 32 + lane];
    float xr[4] = {xv.x, xv.y, xv.z, xv.w};
    float d0 = 0.f, d1 = 0.f, d2 = 0.f;
    int kb = lane * 4;
#pragma unroll
    for (int j = 0; j < 4; j++) {
        const float* wr = Wg + (kb + j) * 3;
        d0 = fmaf(xr[j], wr[0], d0);
        d1 = fmaf(xr[j], wr[1], d1);
        d2 = fmaf(xr[j], wr[2], d2);
    }
#pragma unroll
    for (int off = 16; off; off >>= 1) {
        d0 += __shfl_xor_sync(0xffffffffu, d0, off);
        d1 += __shfl_xor_sync(0xffffffffu, d1, off);
        d2 += __shfl_xor_sync(0xffffffffu, d2, off);
    }
    if (lane == 0) {
        g_G[gwarp * 3 + 0] = 1.f / (1.f + expf(-(d0 + bg[0])));
        g_G[gwarp * 3 + 1] = 1.f / (1.f + expf(-(d1 + bg[1])));
        g_G[gwarp * 3 + 2] = 1.f / (1.f + expf(-(d2 + bg[2])));
    }
}

// ---------------------------------------------------------------------------
// Kernel 3: backward suffix scans -> cM, cS + per-batch active start index.
//   cS_r = -th_r * E_r,   E_r = prod_{u>r} e_u
//   cM_r = -th_r * W_r,   W_r = A_r + e_{r+1} W_{r+1},  A_r = prod_{u>r}(1-a_u)
// grid 8 (one per b), 128 threads (chunks of 8 timesteps).
// ---------------------------------------------------------------------------
__global__ void bwd_kernel() {
    const int b = blockIdx.x;
    const int i = threadIdx.x;          // 0..127, chunk of 8 timesteps
    const int lo = i * 8;
    const float* __restrict__ gb = g_G + (size_t)b * NS * 3;

    float ev[8], av[8], thv[8];
#pragma unroll
    for (int j = 0; j < 8; j++) {
        av[j]  = 1.f - gb[(lo + j) * 3 + 0];
        ev[j]  = gb[(lo + j) * 3 + 1];
        thv[j] = gb[(lo + j) * 3 + 2];
    }
    float e_next = (lo + 8 < NS) ? gb[(lo + 8) * 3 + 1] : 0.f;

    __shared__ float sLe[128], sLa[128], sAa[128], sBa[128];
    __shared__ float sTe[128], sTa[128], sTw[128];

    float Le = 1.f, La = 1.f;
#pragma unroll
    for (int j = 0; j < 8; j++) { Le *= ev[j]; La *= av[j]; }
    sLe[i] = Le; sLa[i] = La;
    __syncthreads();
    if (i == 0) {       // exclusive suffix products across chunks
        float te = 1.f, ta = 1.f;
        for (int c = 127; c >= 0; c--) {
            sTe[c] = te; sTa[c] = ta;
            te *= sLe[c]; ta *= sLa[c];
        }
    }
    __syncthreads();

    float E[8], A[8];
    {
        float re = sTe[i], ra = sTa[i];
#pragma unroll
        for (int j = 7; j >= 0; j--) {
            E[j] = re; A[j] = ra;
            re *= ev[j]; ra *= av[j];
        }
    }
    // local affine composition for W (map: W_tail -> W_{lo})
    float Aa = 1.f, Ba = 0.f;
#pragma unroll
    for (int j = 7; j >= 0; j--) {
        float al = (j == 7) ? e_next : ev[j + 1];
        Aa = al * Aa;
        Ba = fmaf(al, Ba, A[j]);
    }
    sAa[i] = Aa; sBa[i] = Ba;
    __syncthreads();
    if (i == 0) {       // tail W per chunk (value of W at hi(c)+1)
        float w = 0.f;
        for (int c = 127; c >= 0; c--) {
            sTw[c] = w;
            w = fmaf(sAa[c], w, sBa[c]);
        }
    }
    __syncthreads();

    float w = sTw[i];
    int flag = 0;
#pragma unroll
    for (int j = 7; j >= 0; j--) {
        float al = (j == 7) ? e_next : ev[j + 1];
        w = fmaf(al, w, A[j]);                  // = W_{lo+j}
        float cm = -thv[j] * w;
        float cs = -thv[j] * E[j];
        g_cM[b * NS + lo + j] = cm;
        g_cS[b * NS + lo + j] = cs;
        if (fabsf(cm) > 1e-18f || fabsf(cs) > 1e-18f) flag = 1;
    }
    if (flag) atomicMin(&g_tstart[b], lo);
}

// ---------------------------------------------------------------------------
// Kernel 4: forward diagonal scan, parallelized over time via chunked 2x2
// affine composition. state [m;s]_t = A_t [m;s]_{t-1} + b_t.
// grid (4 d-tiles, 8 b), 1024 threads = 32 chunks(warps) x 32 d-lanes.
// ---------------------------------------------------------------------------
__global__ void fwd_scan_kernel(float* __restrict__ y_out) {
    const int b     = blockIdx.y;
    const int dtile = blockIdx.x;
    const int chunk = threadIdx.x >> 5;   // 0..31, 32 timesteps each
    const int lane  = threadIdx.x & 31;   // d within tile
    const int d     = dtile * 32 + lane;
    const size_t base = (size_t)b * NS * ND + d;
    const float* __restrict__ gp = g_G + (size_t)b * NS * 3;
    const int t0 = chunk * 32;

    __shared__ float comp[32][32][6];     // [chunk][lane][m00 m01 m10 m11 v0 v1]

    // ---- phase 1: compose the affine map of this chunk ----
    {
        float m00 = 1.f, m01 = 0.f, m10 = 0.f, m11 = 1.f, w0 = 0.f, w1 = 0.f;
#pragma unroll 4
        for (int j = 0; j < 32; j++) {
            const int t = t0 + j;
            float k  = g_K[base + (size_t)t * ND];
            float vv = g_V[base + (size_t)t * ND];
            float a  = gp[t * 3 + 0];
            float e  = gp[t * 3 + 1];
            float th = gp[t * 3 + 2];
            float thk2 = th * (k * k);
            float p = (1.f - a) - thk2;
            float q = -thk2;
            float c = th * k * vv;
            float e10 = e * m10, e11 = e * m11, ev = fmaf(e, w1, c);
            float n00 = fmaf(p, m00, e10), n01 = fmaf(p, m01, e11);
            float n10 = fmaf(q, m00, e10), n11 = fmaf(q, m01, e11);
            float nv0 = fmaf(p, w0, ev),   nv1 = fmaf(q, w0, ev);
            m00 = n00; m01 = n01; m10 = n10; m11 = n11; w0 = nv0; w1 = nv1;
        }
        comp[chunk][lane][0] = m00; comp[chunk][lane][1] = m01;
        comp[chunk][lane][2] = m10; comp[chunk][lane][3] = m11;
        comp[chunk][lane][4] = w0;  comp[chunk][lane][5] = w1;
    }
    __syncthreads();

    // ---- phase 2: sequential composition across 32 chunks (warp 0) ----
    if (threadIdx.x < 32) {
        const int l = threadIdx.x;
        float x0 = 0.f, x1 = 0.f;
        for (int c = 0; c < 32; c++) {
            float m00 = comp[c][l][0], m01 = comp[c][l][1];
            float m10 = comp[c][l][2], m11 = comp[c][l][3];
            float v0  = comp[c][l][4], v1  = comp[c][l][5];
            comp[c][l][0] = x0;                 // start state of chunk c
            comp[c][l][1] = x1;
            float nx0 = fmaf(m00, x0, fmaf(m01, x1, v0));
            float nx1 = fmaf(m10, x0, fmaf(m11, x1, v1));
            x0 = nx0; x1 = nx1;
        }
    }
    __syncthreads();

    // ---- phase 3: replay chunk from exact start state, emit y and err ----
    {
        float m = comp[chunk][lane][0];
        float s = comp[chunk][lane][1];
#pragma unroll 4
        for (int j = 0; j < 32; j++) {
            const int t = t0 + j;
            const size_t off = base + (size_t)t * ND;
            float k  = g_K[off];
            float vv = g_V[off];
            float qq = g_Q[off];
            float a  = gp[t * 3 + 0];
            float e  = gp[t * 3 + 1];
            float th = gp[t * 3 + 2];
            y_out[off] = qq * m;
            float err = fmaf(k, m, -vv);
            g_Err[off] = err;
            s = fmaf(e, s, -th * (k * err));
            m = fmaf(1.f - a, m, s);
        }
    }
}

// ---------------------------------------------------------------------------
// Kernel 5: M_final/S_final = (c o K)^T @ Err over active range [t_start, NS).
// grid (2 col-halves, 2 which, 8 b), 256 threads, no atomics.
// ---------------------------------------------------------------------------
__global__ void final_kernel(float* __restrict__ out) {
    const int colh  = blockIdx.x;     // 0/1 -> cols [0,64)/[64,128)
    const int which = blockIdx.y;     // 0 -> M (cM), 1 -> S (cS)
    const int b     = blockIdx.z;
    const float* __restrict__ cw = which ? g_cS : g_cM;
    const int tid = threadIdx.x;

    int ts = g_tstart[b];
    if (ts > NS) ts = NS;
    int t0 = ts & ~31;                // align to chunk of 32

    __shared__ float As[32][128];     // (c o K) rows
    __shared__ float Bs[32][64];      // Err cols for this half

    const int tx = tid & 15, ty = tid >> 4;   // 16 x 16 thread tile
    const int i0 = ty * 8, j0 = tx * 4;       // 8 rows x 4 cols per thread
    float acc[8][4];
#pragma unroll
    for (int r = 0; r < 8; r++)
#pragma unroll
        for (int c = 0; c < 4; c++) acc[r][c] = 0.f;

    for (int tc = t0; tc < NS; tc += 32) {
        __syncthreads();
        for (int idx = tid; idx < 32 * 128; idx += 256) {
            int kk = idx >> 7, col = idx & 127;
            size_t t = (size_t)b * NS + tc + kk;
            As[kk][col] = cw[t] * g_K[t * ND + col];
        }
        for (int idx = tid; idx < 32 * 64; idx += 256) {
            int kk = idx >> 6, col = idx & 63;
            size_t t = (size_t)b * NS + tc + kk;
            Bs[kk][col] = g_Err[t * ND + colh * 64 + col];
        }
        __syncthreads();

#pragma unroll 8
        for (int kk = 0; kk < 32; kk++) {
            float avv[8], bvv[4];
            float4 a0 = *(const float4*)&As[kk][i0];
            float4 a1 = *(const float4*)&As[kk][i0 + 4];
            float4 b0 = *(const float4*)&Bs[kk][j0];
            avv[0]=a0.x; avv[1]=a0.y; avv[2]=a0.z; avv[3]=a0.w;
            avv[4]=a1.x; avv[5]=a1.y; avv[6]=a1.z; avv[7]=a1.w;
            bvv[0]=b0.x; bvv[1]=b0.y; bvv[2]=b0.z; bvv[3]=b0.w;
#pragma unroll
            for (int r = 0; r < 8; r++)
#pragma unroll
                for (int c = 0; c < 4; c++)
                    acc[r][c] = fmaf(avv[r], bvv[c], acc[r][c]);
        }
    }

    float* o = out + (size_t)NBS * ND + (size_t)which * NB * ND * ND
                 + (size_t)b * ND * ND + colh * 64;
#pragma unroll
    for (int r = 0; r < 8; r++) {
        float4 res = make_float4(acc[r][0], acc[r][1], acc[r][2], acc[r][3]);
        *(float4*)&o[(i0 + r) * ND + j0] = res;
    }
}

// ---------------------------------------------------------------------------
extern "C" void kernel_launch(void* const* d_in, const int* in_sizes, int n_in,
                              void* d_out, int out_size) {
    const float* x  = (const float*)d_in[0];
    const float* Wk = (const float*)d_in[1];
    const float* Wv = (const float*)d_in[2];
    const float* Wq = (const float*)d_in[3];
    const float* Wg = (const float*)d_in[4];
    const float* bg = (const float*)d_in[5];
    float* out = (float*)d_out;

    void* tsPtr = nullptr;
    cudaGetSymbolAddress(&tsPtr, g_tstart);
    cudaMemsetAsync(tsPtr, 0x7F, sizeof(int) * NB);   // large sentinel

    proj_kernel<<<dim3(128, 3), 256>>>(x, Wk, Wv, Wq);
    gates_kernel<<<1024, 256>>>(x, Wg, bg);
    bwd_kernel<<<8, 128>>>();
    fwd_scan_kernel<<<dim3(4, 8), 1024>>>(out);
    final_kernel<<<dim3(2, 2, 8), 256>>>(out);
}

// round 6
// speedup vs baseline: 4.9720x; 1.0816x over previous
#include <cuda_runtime.h>

#define NB 8
#define NS 1024
#define ND 128
#define NBS (NB*NS)   // 8192
#define NCH 64        // time chunks
#define CLEN 16       // steps per chunk

// scratch (static __device__ allocations only, per harness rules)
__device__ float g_K[NBS*ND];
__device__ float g_V[NBS*ND];
__device__ float g_Q[NBS*ND];
__device__ float g_G[NBS*3];
__device__ float g_Err[NBS*ND];
__device__ float g_cM[NBS];
__device__ float g_cS[NBS];
__device__ float g_comp[NB*NCH*6*ND];   // per-chunk 2x2 affine maps
__device__ float g_start[NB*NCH*2*ND];  // per-chunk start states
__device__ int   g_tstart[NB];

// ---------------------------------------------------------------------------
// packed fp32x2 helpers (Blackwell FFMA2 path, PTX-only)
// ---------------------------------------------------------------------------
__device__ __forceinline__ unsigned long long fma2(unsigned long long a,
                                                   unsigned long long b,
                                                   unsigned long long c) {
    unsigned long long d;
    asm("fma.rn.f32x2 %0, %1, %2, %3;" : "=l"(d) : "l"(a), "l"(b), "l"(c));
    return d;
}
__device__ __forceinline__ float pairsum(unsigned long long v) {
    float lo, hi;
    asm("mov.b64 {%0, %1}, %2;" : "=f"(lo), "=f"(hi) : "l"(v));
    return lo + hi;
}

// ---------------------------------------------------------------------------
// Kernel 1: projections K = x@Wk, V = x@Wv, Q = x@Wq  (f32x2 packed FMA)
// grid (128 row-tiles, 3 matrices), 256 threads, 96KB dynamic smem.
// W staged in smem blocked layout wt[kq][c][4] (kq = k/4), so both x and W
// feed FMA2 as k-parity pairs with zero pack MOVs and conflict-free LDS.128.
// ---------------------------------------------------------------------------
__global__ void __launch_bounds__(256, 2)
proj_kernel(const float* __restrict__ x,
            const float* __restrict__ Wk,
            const float* __restrict__ Wv,
            const float* __restrict__ Wq) {
    extern __shared__ float smem[];
    float*  xs = smem;                       // 64 x 128 floats (32KB)
    float4* wt = (float4*)(smem + 64 * ND);  // 32 x 128 units of 16B (64KB)

    const int tile = blockIdx.x;
    const int mat  = blockIdx.y;
    const float* __restrict__ W = (mat == 0) ? Wk : (mat == 1) ? Wv : Wq;
    float* out = (mat == 0) ? g_K : (mat == 1) ? g_V : g_Q;
    const int tid = threadIdx.x;

    // stage x tile (coalesced float4)
    const float4* x4 = (const float4*)(x + (size_t)tile * 64 * ND);
#pragma unroll
    for (int j = 0; j < 8; j++) {
        int idx = tid + j * 256;            // 2048 float4s
        ((float4*)xs)[idx] = x4[idx];
    }
    // stage W into blocked layout: wt[kq*128 + c] = {W[4kq..4kq+3][c]}
#pragma unroll
    for (int j = 0; j < 16; j++) {
        int u = tid + j * 256;              // 4096 units
        int kq = u >> 7, c = u & 127;
        float4 wv;
        wv.x = W[(4 * kq + 0) * ND + c];
        wv.y = W[(4 * kq + 1) * ND + c];
        wv.z = W[(4 * kq + 2) * ND + c];
        wv.w = W[(4 * kq + 3) * ND + c];
        wt[u] = wv;
    }
    __syncthreads();

    const int lane = tid & 31;
    const int rb   = (tid >> 5) * 8;        // 8 rows per thread
    unsigned long long acc[8][4];
#pragma unroll
    for (int r = 0; r < 8; r++)
#pragma unroll
        for (int c = 0; c < 4; c++) acc[r][c] = 0ull;

#pragma unroll 4
    for (int kq = 0; kq < 32; kq++) {
        ulonglong2 xp[8];
#pragma unroll
        for (int r = 0; r < 8; r++)
            xp[r] = *(const ulonglong2*)&xs[(rb + r) * ND + 4 * kq];
#pragma unroll
        for (int cc = 0; cc < 4; cc++) {
            ulonglong2 wp = ((const ulonglong2*)wt)[kq * ND + lane + 32 * cc];
#pragma unroll
            for (int r = 0; r < 8; r++) {
                acc[r][cc] = fma2(xp[r].x, wp.x, acc[r][cc]);
                acc[r][cc] = fma2(xp[r].y, wp.y, acc[r][cc]);
            }
        }
    }
#pragma unroll
    for (int r = 0; r < 8; r++)
#pragma unroll
        for (int cc = 0; cc < 4; cc++)
            out[(size_t)(tile * 64 + rb + r) * ND + lane + 32 * cc] =
                pairsum(acc[r][cc]);
}

// ---------------------------------------------------------------------------
// Kernel 2: gates = sigmoid(x @ Wg + bg), one warp per row
// ---------------------------------------------------------------------------
__global__ void gates_kernel(const float* __restrict__ x,
                             const float* __restrict__ Wg,
                             const float* __restrict__ bg) {
    int gwarp = (blockIdx.x * blockDim.x + threadIdx.x) >> 5;
    int lane  = threadIdx.x & 31;
    if (gwarp >= NBS) return;
    float4 xv = ((const float4*)x)[gwarp * 32 + lane];
    float xr[4] = {xv.x, xv.y, xv.z, xv.w};
    float d0 = 0.f, d1 = 0.f, d2 = 0.f;
    int kb = lane * 4;
#pragma unroll
    for (int j = 0; j < 4; j++) {
        const float* wr = Wg + (kb + j) * 3;
        d0 = fmaf(xr[j], wr[0], d0);
        d1 = fmaf(xr[j], wr[1], d1);
        d2 = fmaf(xr[j], wr[2], d2);
    }
#pragma unroll
    for (int off = 16; off; off >>= 1) {
        d0 += __shfl_xor_sync(0xffffffffu, d0, off);
        d1 += __shfl_xor_sync(0xffffffffu, d1, off);
        d2 += __shfl_xor_sync(0xffffffffu, d2, off);
    }
    if (lane == 0) {
        g_G[gwarp * 3 + 0] = 1.f / (1.f + expf(-(d0 + bg[0])));
        g_G[gwarp * 3 + 1] = 1.f / (1.f + expf(-(d1 + bg[1])));
        g_G[gwarp * 3 + 2] = 1.f / (1.f + expf(-(d2 + bg[2])));
    }
}

// ---------------------------------------------------------------------------
// Kernel 3: backward suffix scans -> cM, cS + per-batch active start index.
// grid 8 (one per b), 128 threads (chunks of 8 timesteps).
// ---------------------------------------------------------------------------
__global__ void bwd_kernel() {
    const int b = blockIdx.x;
    const int i = threadIdx.x;          // 0..127, chunk of 8 timesteps
    const int lo = i * 8;
    const float* __restrict__ gb = g_G + (size_t)b * NS * 3;

    float ev[8], av[8], thv[8];
#pragma unroll
    for (int j = 0; j < 8; j++) {
        av[j]  = 1.f - gb[(lo + j) * 3 + 0];
        ev[j]  = gb[(lo + j) * 3 + 1];
        thv[j] = gb[(lo + j) * 3 + 2];
    }
    float e_next = (lo + 8 < NS) ? gb[(lo + 8) * 3 + 1] : 0.f;

    __shared__ float sLe[128], sLa[128], sAa[128], sBa[128];
    __shared__ float sTe[128], sTa[128], sTw[128];
    __shared__ int   smin[4];

    float Le = 1.f, La = 1.f;
#pragma unroll
    for (int j = 0; j < 8; j++) { Le *= ev[j]; La *= av[j]; }
    sLe[i] = Le; sLa[i] = La;
    __syncthreads();
    if (i == 0) {       // exclusive suffix products across chunks
        float te = 1.f, ta = 1.f;
        for (int c = 127; c >= 0; c--) {
            sTe[c] = te; sTa[c] = ta;
            te *= sLe[c]; ta *= sLa[c];
        }
    }
    __syncthreads();

    float E[8], A[8];
    {
        float re = sTe[i], ra = sTa[i];
#pragma unroll
        for (int j = 7; j >= 0; j--) {
            E[j] = re; A[j] = ra;
            re *= ev[j]; ra *= av[j];
        }
    }
    float Aa = 1.f, Ba = 0.f;
#pragma unroll
    for (int j = 7; j >= 0; j--) {
        float al = (j == 7) ? e_next : ev[j + 1];
        Aa = al * Aa;
        Ba = fmaf(al, Ba, A[j]);
    }
    sAa[i] = Aa; sBa[i] = Ba;
    __syncthreads();
    if (i == 0) {       // tail W per chunk
        float w = 0.f;
        for (int c = 127; c >= 0; c--) {
            sTw[c] = w;
            w = fmaf(sAa[c], w, sBa[c]);
        }
    }
    __syncthreads();

    float w = sTw[i];
    int flag = 0;
#pragma unroll
    for (int j = 7; j >= 0; j--) {
        float al = (j == 7) ? e_next : ev[j + 1];
        w = fmaf(al, w, A[j]);                  // = W_{lo+j}
        float cm = -thv[j] * w;
        float cs = -thv[j] * E[j];
        g_cM[b * NS + lo + j] = cm;
        g_cS[b * NS + lo + j] = cs;
        if (fabsf(cm) > 1e-18f || fabsf(cs) > 1e-18f) flag = 1;
    }
    // block-wide min of active start (no global memset needed)
    int myv = flag ? lo : 0x7FFFFFFF;
    myv = __reduce_min_sync(0xffffffffu, myv);
    if ((i & 31) == 0) smin[i >> 5] = myv;
    __syncthreads();
    if (i == 0) {
        int r = smin[0];
        r = min(r, smin[1]); r = min(r, smin[2]); r = min(r, smin[3]);
        g_tstart[b] = r;
    }
}

// ---------------------------------------------------------------------------
// Forward scan phase 1: per-chunk 2x2 affine map composition.
// grid (64 chunks, 8 b), 128 threads (d). Full-chip parallel.
// state [m;s]_t = T_t [m;s]_{t-1} + (c,c);  T = [[p,e],[q,e]]
// ---------------------------------------------------------------------------
__global__ void scan_p1() {
    const int ch = blockIdx.x, b = blockIdx.y;
    const int d  = threadIdx.x;
    const int t0 = ch * CLEN;
    __shared__ float sg[CLEN * 3];
    if (d < CLEN * 3) sg[d] = g_G[(size_t)b * NS * 3 + t0 * 3 + d];
    __syncthreads();

    const size_t base = (size_t)b * NS * ND + d;
    float m00 = 1.f, m01 = 0.f, m10 = 0.f, m11 = 1.f, w0 = 0.f, w1 = 0.f;
#pragma unroll
    for (int j = 0; j < CLEN; j++) {
        float k  = g_K[base + (size_t)(t0 + j) * ND];
        float vv = g_V[base + (size_t)(t0 + j) * ND];
        float a = sg[j * 3 + 0], e = sg[j * 3 + 1], th = sg[j * 3 + 2];
        float thk2 = th * (k * k);
        float p = (1.f - a) - thk2;
        float q = -thk2;
        float c = th * k * vv;
        float e10 = e * m10, e11 = e * m11, ev = fmaf(e, w1, c);
        float n00 = fmaf(p, m00, e10), n01 = fmaf(p, m01, e11);
        float n10 = fmaf(q, m00, e10), n11 = fmaf(q, m01, e11);
        float nv0 = fmaf(p, w0, ev),   nv1 = fmaf(q, w0, ev);
        m00 = n00; m01 = n01; m10 = n10; m11 = n11; w0 = nv0; w1 = nv1;
    }
    const size_t cb = ((size_t)(b * NCH + ch) * 6) * ND + d;
    g_comp[cb + 0 * ND] = m00; g_comp[cb + 1 * ND] = m01;
    g_comp[cb + 2 * ND] = m10; g_comp[cb + 3 * ND] = m11;
    g_comp[cb + 4 * ND] = w0;  g_comp[cb + 5 * ND] = w1;
}

// ---------------------------------------------------------------------------
// Forward scan phase 2: chunk-boundary start states, hierarchical.
// grid 8 (b), 1024 threads = 8 subs x 128 d. Each sub covers 8 chunks.
// ---------------------------------------------------------------------------
__global__ void scan_p2() {
    const int b   = blockIdx.x;
    const int d   = threadIdx.x & 127;
    const int sub = threadIdx.x >> 7;     // 0..7

    __shared__ float scomp[8][128][6];
    __shared__ float sx[8][128][2];

    // pass A: compose this sub-block's 8 chunk maps
    {
        float r00 = 1.f, r01 = 0.f, r10 = 0.f, r11 = 1.f, rv0 = 0.f, rv1 = 0.f;
#pragma unroll
        for (int i = 0; i < 8; i++) {
            const int c = sub * 8 + i;
            const size_t cb = ((size_t)(b * NCH + c) * 6) * ND + d;
            float t00 = g_comp[cb + 0 * ND], t01 = g_comp[cb + 1 * ND];
            float t10 = g_comp[cb + 2 * ND], t11 = g_comp[cb + 3 * ND];
            float tv0 = g_comp[cb + 4 * ND], tv1 = g_comp[cb + 5 * ND];
            float n00 = fmaf(t00, r00, t01 * r10);
            float n01 = fmaf(t00, r01, t01 * r11);
            float n10 = fmaf(t10, r00, t11 * r10);
            float n11 = fmaf(t10, r01, t11 * r11);
            float nv0 = fmaf(t00, rv0, fmaf(t01, rv1, tv0));
            float nv1 = fmaf(t10, rv0, fmaf(t11, rv1, tv1));
            r00 = n00; r01 = n01; r10 = n10; r11 = n11; rv0 = nv0; rv1 = nv1;
        }
        scomp[sub][d][0] = r00; scomp[sub][d][1] = r01;
        scomp[sub][d][2] = r10; scomp[sub][d][3] = r11;
        scomp[sub][d][4] = rv0; scomp[sub][d][5] = rv1;
    }
    __syncthreads();

    // serial across 8 subs (128 threads, one per d)
    if (threadIdx.x < 128) {
        float x0 = 0.f, x1 = 0.f;
#pragma unroll
        for (int s = 0; s < 8; s++) {
            sx[s][d][0] = x0; sx[s][d][1] = x1;
            float t00 = scomp[s][d][0], t01 = scomp[s][d][1];
            float t10 = scomp[s][d][2], t11 = scomp[s][d][3];
            float nx0 = fmaf(t00, x0, fmaf(t01, x1, scomp[s][d][4]));
            float nx1 = fmaf(t10, x0, fmaf(t11, x1, scomp[s][d][5]));
            x0 = nx0; x1 = nx1;
        }
    }
    __syncthreads();

    // pass B: walk 8 chunks, emit per-chunk start state
    {
        float x0 = sx[sub][d][0], x1 = sx[sub][d][1];
#pragma unroll
        for (int i = 0; i < 8; i++) {
            const int c = sub * 8 + i;
            const size_t sb = ((size_t)(b * NCH + c) * 2) * ND + d;
            g_start[sb] = x0; g_start[sb + ND] = x1;
            const size_t cb = ((size_t)(b * NCH + c) * 6) * ND + d;
            float t00 = g_comp[cb + 0 * ND], t01 = g_comp[cb + 1 * ND];
            float t10 = g_comp[cb + 2 * ND], t11 = g_comp[cb + 3 * ND];
            float nx0 = fmaf(t00, x0, fmaf(t01, x1, g_comp[cb + 4 * ND]));
            float nx1 = fmaf(t10, x0, fmaf(t11, x1, g_comp[cb + 5 * ND]));
            x0 = nx0; x1 = nx1;
        }
    }
}

// ---------------------------------------------------------------------------
// Forward scan phase 3: replay each chunk from its start state, emit y / err.
// grid (64, 8), 128 threads. Full-chip parallel.
// ---------------------------------------------------------------------------
__global__ void scan_p3(float* __restrict__ y_out) {
    const int ch = blockIdx.x, b = blockIdx.y;
    const int d  = threadIdx.x;
    const int t0 = ch * CLEN;
    __shared__ float sg[CLEN * 3];
    if (d < CLEN * 3) sg[d] = g_G[(size_t)b * NS * 3 + t0 * 3 + d];
    __syncthreads();

    const size_t base = (size_t)b * NS * ND + d;
    const size_t sb = ((size_t)(b * NCH + ch) * 2) * ND + d;
    float m = g_start[sb], s = g_start[sb + ND];
#pragma unroll
    for (int j = 0; j < CLEN; j++) {
        const size_t off = base + (size_t)(t0 + j) * ND;
        float k  = g_K[off];
        float vv = g_V[off];
        float qq = g_Q[off];
        float a = sg[j * 3 + 0], e = sg[j * 3 + 1], th = sg[j * 3 + 2];
        y_out[off] = qq * m;
        float err = fmaf(k, m, -vv);
        g_Err[off] = err;
        s = fmaf(e, s, -th * (k * err));
        m = fmaf(1.f - a, m, s);
    }
}

// ---------------------------------------------------------------------------
// Kernel 5: M_final/S_final = (c o K)^T @ Err over active range [t_start, NS).
// grid (2 col-halves, 2 which, 8 b), 256 threads, no atomics.
// ---------------------------------------------------------------------------
__global__ void final_kernel(float* __restrict__ out) {
    const int colh  = blockIdx.x;
    const int which = blockIdx.y;     // 0 -> M (cM), 1 -> S (cS)
    const int b     = blockIdx.z;
    const float* __restrict__ cw = which ? g_cS : g_cM;
    const int tid = threadIdx.x;

    int ts = g_tstart[b];
    if (ts > NS) ts = NS;
    int t0 = ts & ~31;

    __shared__ float As[32][128];
    __shared__ float Bs[32][64];

    const int tx = tid & 15, ty = tid >> 4;
    const int i0 = ty * 8, j0 = tx * 4;
    float acc[8][4];
#pragma unroll
    for (int r = 0; r < 8; r++)
#pragma unroll
        for (int c = 0; c < 4; c++) acc[r][c] = 0.f;

    for (int tc = t0; tc < NS; tc += 32) {
        __syncthreads();
        for (int idx = tid; idx < 32 * 128; idx += 256) {
            int kk = idx >> 7, col = idx & 127;
            size_t t = (size_t)b * NS + tc + kk;
            As[kk][col] = cw[t] * g_K[t * ND + col];
        }
        for (int idx = tid; idx < 32 * 64; idx += 256) {
            int kk = idx >> 6, col = idx & 63;
            size_t t = (size_t)b * NS + tc + kk;
            Bs[kk][col] = g_Err[t * ND + colh * 64 + col];
        }
        __syncthreads();

#pragma unroll 8
        for (int kk = 0; kk < 32; kk++) {
            float avv[8], bvv[4];
            float4 a0 = *(const float4*)&As[kk][i0];
            float4 a1 = *(const float4*)&As[kk][i0 + 4];
            float4 b0 = *(const float4*)&Bs[kk][j0];
            avv[0]=a0.x; avv[1]=a0.y; avv[2]=a0.z; avv[3]=a0.w;
            avv[4]=a1.x; avv[5]=a1.y; avv[6]=a1.z; avv[7]=a1.w;
            bvv[0]=b0.x; bvv[1]=b0.y; bvv[2]=b0.z; bvv[3]=b0.w;
#pragma unroll
            for (int r = 0; r < 8; r++)
#pragma unroll
                for (int c = 0; c < 4; c++)
                    acc[r][c] = fmaf(avv[r], bvv[c], acc[r][c]);
        }
    }

    float* o = out + (size_t)NBS * ND + (size_t)which * NB * ND * ND
                 + (size_t)b * ND * ND + colh * 64;
#pragma unroll
    for (int r = 0; r < 8; r++) {
        float4 res = make_float4(acc[r][0], acc[r][1], acc[r][2], acc[r][3]);
        *(float4*)&o[(i0 + r) * ND + j0] = res;
    }
}

// ---------------------------------------------------------------------------
extern "C" void kernel_launch(void* const* d_in, const int* in_sizes, int n_in,
                              void* d_out, int out_size) {
    const float* x  = (const float*)d_in[0];
    const float* Wk = (const float*)d_in[1];
    const float* Wv = (const float*)d_in[2];
    const float* Wq = (const float*)d_in[3];
    const float* Wg = (const float*)d_in[4];
    const float* bg = (const float*)d_in[5];
    float* out = (float*)d_out;

    const int proj_smem = (64 * ND + 32 * ND * 4) * (int)sizeof(float); // 96KB
    cudaFuncSetAttribute(proj_kernel,
                         cudaFuncAttributeMaxDynamicSharedMemorySize, proj_smem);

    proj_kernel<<<dim3(128, 3), 256, proj_smem>>>(x, Wk, Wv, Wq);
    gates_kernel<<<1024, 256>>>(x, Wg, bg);
    bwd_kernel<<<8, 128>>>();
    scan_p1<<<dim3(NCH, NB), 128>>>();
    scan_p2<<<NB, 1024>>>();
    scan_p3<<<dim3(NCH, NB), 128>>>(out);
    final_kernel<<<dim3(2, 2, 8), 256>>>(out);
}

// round 10
// speedup vs baseline: 5.4537x; 1.0969x over previous
#include <cuda_runtime.h>

#define NB 8
#define NS 1024
#define ND 128
#define NBS (NB*NS)   // 8192
#define NCH 128       // time chunks
#define CLEN 8        // steps per chunk

// scratch (static __device__ allocations only, per harness rules)
__device__ float g_K[NBS*ND];
__device__ float g_V[NBS*ND];
__device__ float g_Q[NBS*ND];
__device__ float g_G[NBS*3];
__device__ float g_Err[NBS*ND];
__device__ float g_cM[NBS];
__device__ float g_cS[NBS];
__device__ float g_comp[NB*NCH*6*ND];   // per-chunk 2x2 affine maps
__device__ float g_start[NB*NCH*2*ND];  // per-chunk start states
__device__ int   g_tstart[NB];

// ---------------------------------------------------------------------------
// packed fp32x2 helpers (Blackwell FFMA2 path, PTX-only)
// ---------------------------------------------------------------------------
__device__ __forceinline__ unsigned long long fma2(unsigned long long a,
                                                   unsigned long long b,
                                                   unsigned long long c) {
    unsigned long long d;
    asm("fma.rn.f32x2 %0, %1, %2, %3;" : "=l"(d) : "l"(a), "l"(b), "l"(c));
    return d;
}
__device__ __forceinline__ float pairsum(unsigned long long v) {
    float lo, hi;
    asm("mov.b64 {%0, %1}, %2;" : "=f"(lo), "=f"(hi) : "l"(v));
    return lo + hi;
}

// ---------------------------------------------------------------------------
// Launch 1: projections K/V/Q (f32x2 packed FMA) + gates, one grid.
// grid (128, 4): y<3 -> proj row-tile for matrix y; y==3 -> gates for 64 rows.
// ---------------------------------------------------------------------------
__global__ void __launch_bounds__(256, 2)
proj_gates_kernel(const float* __restrict__ x,
                  const float* __restrict__ Wk,
                  const float* __restrict__ Wv,
                  const float* __restrict__ Wq,
                  const float* __restrict__ Wg,
                  const float* __restrict__ bg) {
    const int tid = threadIdx.x;
    const int mat = blockIdx.y;

    if (mat == 3) {
        // ---- gates: sigmoid(x @ Wg + bg); 8 warps x 8 rows = 64 rows/block
        const int warp = tid >> 5, lane = tid & 31;
        const float b0 = bg[0], b1 = bg[1], b2 = bg[2];
        const int kb = lane * 4;
        float wr0[4], wr1[4], wr2[4];
#pragma unroll
        for (int j = 0; j < 4; j++) {
            const float* wr = Wg + (kb + j) * 3;
            wr0[j] = wr[0]; wr1[j] = wr[1]; wr2[j] = wr[2];
        }
#pragma unroll
        for (int r = 0; r < 8; r++) {
            int row = blockIdx.x * 64 + warp * 8 + r;
            float4 xv = ((const float4*)x)[row * 32 + lane];
            float xr[4] = {xv.x, xv.y, xv.z, xv.w};
            float d0 = 0.f, d1 = 0.f, d2 = 0.f;
#pragma unroll
            for (int j = 0; j < 4; j++) {
                d0 = fmaf(xr[j], wr0[j], d0);
                d1 = fmaf(xr[j], wr1[j], d1);
                d2 = fmaf(xr[j], wr2[j], d2);
            }
#pragma unroll
            for (int off = 16; off; off >>= 1) {
                d0 += __shfl_xor_sync(0xffffffffu, d0, off);
                d1 += __shfl_xor_sync(0xffffffffu, d1, off);
                d2 += __shfl_xor_sync(0xffffffffu, d2, off);
            }
            if (lane == 0) {
                g_G[row * 3 + 0] = 1.f / (1.f + expf(-(d0 + b0)));
                g_G[row * 3 + 1] = 1.f / (1.f + expf(-(d1 + b1)));
                g_G[row * 3 + 2] = 1.f / (1.f + expf(-(d2 + b2)));
            }
        }
        return;
    }

    // ---- projection path
    extern __shared__ float smem[];
    float*  xs = smem;                       // 64 x 128 floats (32KB)
    float4* wt = (float4*)(smem + 64 * ND);  // 32 x 128 units of 16B (64KB)

    const int tile = blockIdx.x;
    const float* __restrict__ W = (mat == 0) ? Wk : (mat == 1) ? Wv : Wq;
    float* out = (mat == 0) ? g_K : (mat == 1) ? g_V : g_Q;

    const float4* x4 = (const float4*)(x + (size_t)tile * 64 * ND);
#pragma unroll
    for (int j = 0; j < 8; j++) {
        int idx = tid + j * 256;            // 2048 float4s
        ((float4*)xs)[idx] = x4[idx];
    }
#pragma unroll
    for (int j = 0; j < 16; j++) {
        int u = tid + j * 256;              // 4096 units
        int kq = u >> 7, c = u & 127;
        float4 wv;
        wv.x = W[(4 * kq + 0) * ND + c];
        wv.y = W[(4 * kq + 1) * ND + c];
        wv.z = W[(4 * kq + 2) * ND + c];
        wv.w = W[(4 * kq + 3) * ND + c];
        wt[u] = wv;
    }
    __syncthreads();

    const int lane = tid & 31;
    const int rb   = (tid >> 5) * 8;        // 8 rows per thread
    unsigned long long acc[8][4];
#pragma unroll
    for (int r = 0; r < 8; r++)
#pragma unroll
        for (int c = 0; c < 4; c++) acc[r][c] = 0ull;

#pragma unroll 4
    for (int kq = 0; kq < 32; kq++) {
        ulonglong2 xp[8];
#pragma unroll
        for (int r = 0; r < 8; r++)
            xp[r] = *(const ulonglong2*)&xs[(rb + r) * ND + 4 * kq];
#pragma unroll
        for (int cc = 0; cc < 4; cc++) {
            ulonglong2 wp = ((const ulonglong2*)wt)[kq * ND + lane + 32 * cc];
#pragma unroll
            for (int r = 0; r < 8; r++) {
                acc[r][cc] = fma2(xp[r].x, wp.x, acc[r][cc]);
                acc[r][cc] = fma2(xp[r].y, wp.y, acc[r][cc]);
            }
        }
    }
#pragma unroll
    for (int r = 0; r < 8; r++)
#pragma unroll
        for (int cc = 0; cc < 4; cc++)
            out[(size_t)(tile * 64 + rb + r) * ND + lane + 32 * cc] =
                pairsum(acc[r][cc]);
}

// ---------------------------------------------------------------------------
// Launch 2: grid (NCH+1, 8), 128 threads.
//   bx < NCH  -> forward-scan phase 1 (per-chunk 2x2 affine map, CLEN=8)
//   bx == NCH -> backward suffix scans -> cM, cS, tstart (per batch)
// ---------------------------------------------------------------------------
__global__ void bwd_p1_kernel() {
    const int bx = blockIdx.x, b = blockIdx.y;

    if (bx < NCH) {
        // ---------------- phase 1: chunk affine maps ----------------
        const int ch = bx, d = threadIdx.x;
        const int t0 = ch * CLEN;
        __shared__ float sg[CLEN * 3];
        if (d < CLEN * 3) sg[d] = g_G[(size_t)b * NS * 3 + t0 * 3 + d];
        __syncthreads();

        const size_t base = (size_t)b * NS * ND + d;
        float kv[CLEN], vv[CLEN];
#pragma unroll
        for (int j = 0; j < CLEN; j++) kv[j] = g_K[base + (size_t)(t0 + j) * ND];
#pragma unroll
        for (int j = 0; j < CLEN; j++) vv[j] = g_V[base + (size_t)(t0 + j) * ND];

        float m00 = 1.f, m01 = 0.f, m10 = 0.f, m11 = 1.f, w0 = 0.f, w1 = 0.f;
#pragma unroll
        for (int j = 0; j < CLEN; j++) {
            float k = kv[j], v = vv[j];
            float a = sg[j * 3 + 0], e = sg[j * 3 + 1], th = sg[j * 3 + 2];
            float thk2 = th * (k * k);
            float p = (1.f - a) - thk2;
            float q = -thk2;
            float c = th * k * v;
            float e10 = e * m10, e11 = e * m11, ev = fmaf(e, w1, c);
            float n00 = fmaf(p, m00, e10), n01 = fmaf(p, m01, e11);
            float n10 = fmaf(q, m00, e10), n11 = fmaf(q, m01, e11);
            float nv0 = fmaf(p, w0, ev),   nv1 = fmaf(q, w0, ev);
            m00 = n00; m01 = n01; m10 = n10; m11 = n11; w0 = nv0; w1 = nv1;
        }
        const size_t cb = ((size_t)(b * NCH + ch) * 6) * ND + d;
        g_comp[cb + 0 * ND] = m00; g_comp[cb + 1 * ND] = m01;
        g_comp[cb + 2 * ND] = m10; g_comp[cb + 3 * ND] = m11;
        g_comp[cb + 4 * ND] = w0;  g_comp[cb + 5 * ND] = w1;
        return;
    }

    // ---------------- backward suffix scans (per batch) ----------------
    const int i = threadIdx.x;          // 0..127, chunk of 8 timesteps
    const int lo = i * 8;
    const float* __restrict__ gb = g_G + (size_t)b * NS * 3;

    float ev[8], av[8], thv[8];
#pragma unroll
    for (int j = 0; j < 8; j++) {
        av[j]  = 1.f - gb[(lo + j) * 3 + 0];
        ev[j]  = gb[(lo + j) * 3 + 1];
        thv[j] = gb[(lo + j) * 3 + 2];
    }
    float e_next = (lo + 8 < NS) ? gb[(lo + 8) * 3 + 1] : 0.f;

    __shared__ float sLe[128], sLa[128], sAa[128], sBa[128];
    __shared__ float sTe[128], sTa[128], sTw[128];
    __shared__ int   smin[4];

    float Le = 1.f, La = 1.f;
#pragma unroll
    for (int j = 0; j < 8; j++) { Le *= ev[j]; La *= av[j]; }
    sLe[i] = Le; sLa[i] = La;
    __syncthreads();
    if (i == 0) {       // exclusive suffix products across chunks
        float te = 1.f, ta = 1.f;
        for (int c = 127; c >= 0; c--) {
            sTe[c] = te; sTa[c] = ta;
            te *= sLe[c]; ta *= sLa[c];
        }
    }
    __syncthreads();

    float E[8], A[8];
    {
        float re = sTe[i], ra = sTa[i];
#pragma unroll
        for (int j = 7; j >= 0; j--) {
            E[j] = re; A[j] = ra;
            re *= ev[j]; ra *= av[j];
        }
    }
    float Aa = 1.f, Ba = 0.f;
#pragma unroll
    for (int j = 7; j >= 0; j--) {
        float al = (j == 7) ? e_next : ev[j + 1];
        Aa = al * Aa;
        Ba = fmaf(al, Ba, A[j]);
    }
    sAa[i] = Aa; sBa[i] = Ba;
    __syncthreads();
    if (i == 0) {       // tail W per chunk
        float w = 0.f;
        for (int c = 127; c >= 0; c--) {
            sTw[c] = w;
            w = fmaf(sAa[c], w, sBa[c]);
        }
    }
    __syncthreads();

    float w = sTw[i];
    int flag = 0;
#pragma unroll
    for (int j = 7; j >= 0; j--) {
        float al = (j == 7) ? e_next : ev[j + 1];
        w = fmaf(al, w, A[j]);                  // = W_{lo+j}
        float cm = -thv[j] * w;
        float cs = -thv[j] * E[j];
        g_cM[b * NS + lo + j] = cm;
        g_cS[b * NS + lo + j] = cs;
        if (fabsf(cm) > 1e-18f || fabsf(cs) > 1e-18f) flag = 1;
    }
    int myv = flag ? lo : 0x7FFFFFFF;
    myv = __reduce_min_sync(0xffffffffu, myv);
    if ((i & 31) == 0) smin[i >> 5] = myv;
    __syncthreads();
    if (i == 0) {
        int r = smin[0];
        r = min(r, smin[1]); r = min(r, smin[2]); r = min(r, smin[3]);
        g_tstart[b] = r;
    }
}

// ---------------------------------------------------------------------------
// Launch 3: chunk-boundary start states, hierarchical.
// grid 8 (b), 1024 threads = 8 subs x 128 d. Each sub covers 16 chunks.
// ---------------------------------------------------------------------------
__global__ void scan_p2() {
    const int b   = blockIdx.x;
    const int d   = threadIdx.x & 127;
    const int sub = threadIdx.x >> 7;     // 0..7

    __shared__ float scomp[8][128][6];
    __shared__ float sx[8][128][2];

    // pass A: compose this sub-block's 16 chunk maps
    {
        float r00 = 1.f, r01 = 0.f, r10 = 0.f, r11 = 1.f, rv0 = 0.f, rv1 = 0.f;
#pragma unroll
        for (int i = 0; i < 16; i++) {
            const int c = sub * 16 + i;
            const size_t cb = ((size_t)(b * NCH + c) * 6) * ND + d;
            float t00 = g_comp[cb + 0 * ND], t01 = g_comp[cb + 1 * ND];
            float t10 = g_comp[cb + 2 * ND], t11 = g_comp[cb + 3 * ND];
            float tv0 = g_comp[cb + 4 * ND], tv1 = g_comp[cb + 5 * ND];
            float n00 = fmaf(t00, r00, t01 * r10);
            float n01 = fmaf(t00, r01, t01 * r11);
            float n10 = fmaf(t10, r00, t11 * r10);
            float n11 = fmaf(t10, r01, t11 * r11);
            float nv0 = fmaf(t00, rv0, fmaf(t01, rv1, tv0));
            float nv1 = fmaf(t10, rv0, fmaf(t11, rv1, tv1));
            r00 = n00; r01 = n01; r10 = n10; r11 = n11; rv0 = nv0; rv1 = nv1;
        }
        scomp[sub][d][0] = r00; scomp[sub][d][1] = r01;
        scomp[sub][d][2] = r10; scomp[sub][d][3] = r11;
        scomp[sub][d][4] = rv0; scomp[sub][d][5] = rv1;
    }
    __syncthreads();

    // serial across 8 subs (128 threads, one per d)
    if (threadIdx.x < 128) {
        float x0 = 0.f, x1 = 0.f;
#pragma unroll
        for (int s = 0; s < 8; s++) {
            sx[s][d][0] = x0; sx[s][d][1] = x1;
            float t00 = scomp[s][d][0], t01 = scomp[s][d][1];
            float t10 = scomp[s][d][2], t11 = scomp[s][d][3];
            float nx0 = fmaf(t00, x0, fmaf(t01, x1, scomp[s][d][4]));
            float nx1 = fmaf(t10, x0, fmaf(t11, x1, scomp[s][d][5]));
            x0 = nx0; x1 = nx1;
        }
    }
    __syncthreads();

    // pass B: walk 16 chunks, emit per-chunk start state
    {
        float x0 = sx[sub][d][0], x1 = sx[sub][d][1];
#pragma unroll
        for (int i = 0; i < 16; i++) {
            const int c = sub * 16 + i;
            const size_t sb = ((size_t)(b * NCH + c) * 2) * ND + d;
            g_start[sb] = x0; g_start[sb + ND] = x1;
            const size_t cb = ((size_t)(b * NCH + c) * 6) * ND + d;
            float t00 = g_comp[cb + 0 * ND], t01 = g_comp[cb + 1 * ND];
            float t10 = g_comp[cb + 2 * ND], t11 = g_comp[cb + 3 * ND];
            float nx0 = fmaf(t00, x0, fmaf(t01, x1, g_comp[cb + 4 * ND]));
            float nx1 = fmaf(t10, x0, fmaf(t11, x1, g_comp[cb + 5 * ND]));
            x0 = nx0; x1 = nx1;
        }
    }
}

// ---------------------------------------------------------------------------
// Launch 4: replay each chunk from its start state, emit y / err.
// grid (128, 8), 128 threads. Err stores gated by per-batch active range.
// ---------------------------------------------------------------------------
__global__ void scan_p3(float* __restrict__ y_out) {
    const int ch = blockIdx.x, b = blockIdx.y;
    const int d  = threadIdx.x;
    const int t0 = ch * CLEN;
    __shared__ float sg[CLEN * 3];
    __shared__ int sts;
    if (d < CLEN * 3) sg[d] = g_G[(size_t)b * NS * 3 + t0 * 3 + d];
    if (d == 0) sts = g_tstart[b];
    __syncthreads();

    int ts = sts;
    if (ts > NS) ts = NS;
    const bool storeErr = (t0 + CLEN) > (ts & ~31);

    const size_t base = (size_t)b * NS * ND + d;
    const size_t sb = ((size_t)(b * NCH + ch) * 2) * ND + d;
    float m = g_start[sb], s = g_start[sb + ND];

    float kv[CLEN], vv[CLEN], qv[CLEN];
#pragma unroll
    for (int j = 0; j < CLEN; j++) kv[j] = g_K[base + (size_t)(t0 + j) * ND];
#pragma unroll
    for (int j = 0; j < CLEN; j++) vv[j] = g_V[base + (size_t)(t0 + j) * ND];
#pragma unroll
    for (int j = 0; j < CLEN; j++) qv[j] = g_Q[base + (size_t)(t0 + j) * ND];

#pragma unroll
    for (int j = 0; j < CLEN; j++) {
        const size_t off = base + (size_t)(t0 + j) * ND;
        float a = sg[j * 3 + 0], e = sg[j * 3 + 1], th = sg[j * 3 + 2];
        y_out[off] = qv[j] * m;
        float err = fmaf(kv[j], m, -vv[j]);
        if (storeErr) g_Err[off] = err;
        s = fmaf(e, s, -th * (kv[j] * err));
        m = fmaf(1.f - a, m, s);
    }
}

// ---------------------------------------------------------------------------
// Launch 5: M_final/S_final = (c o K)^T @ Err over active range [t_start, NS).
// grid (2 col-halves, 2 which, 8 b), 256 threads, no atomics.
// ---------------------------------------------------------------------------
__global__ void final_kernel(float* __restrict__ out) {
    const int colh  = blockIdx.x;
    const int which = blockIdx.y;     // 0 -> M (cM), 1 -> S (cS)
    const int b     = blockIdx.z;
    const float* __restrict__ cw = which ? g_cS : g_cM;
    const int tid = threadIdx.x;

    int ts = g_tstart[b];
    if (ts > NS) ts = NS;
    int t0 = ts & ~31;

    __shared__ float As[32][128];
    __shared__ float Bs[32][64];

    const int tx = tid & 15, ty = tid >> 4;
    const int i0 = ty * 8, j0 = tx * 4;
    float acc[8][4];
#pragma unroll
    for (int r = 0; r < 8; r++)
#pragma unroll
        for (int c = 0; c < 4; c++) acc[r][c] = 0.f;

    for (int tc = t0; tc < NS; tc += 32) {
        __syncthreads();
        for (int idx = tid; idx < 32 * 128; idx += 256) {
            int kk = idx >> 7, col = idx & 127;
            size_t t = (size_t)b * NS + tc + kk;
            As[kk][col] = cw[t] * g_K[t * ND + col];
        }
        for (int idx = tid; idx < 32 * 64; idx += 256) {
            int kk = idx >> 6, col = idx & 63;
            size_t t = (size_t)b * NS + tc + kk;
            Bs[kk][col] = g_Err[t * ND + colh * 64 + col];
        }
        __syncthreads();

#pragma unroll 8
        for (int kk = 0; kk < 32; kk++) {
            float avv[8], bvv[4];
            float4 a0 = *(const float4*)&As[kk][i0];
            float4 a1 = *(const float4*)&As[kk][i0 + 4];
            float4 b0 = *(const float4*)&Bs[kk][j0];
            avv[0]=a0.x; avv[1]=a0.y; avv[2]=a0.z; avv[3]=a0.w;
            avv[4]=a1.x; avv[5]=a1.y; avv[6]=a1.z; avv[7]=a1.w;
            bvv[0]=b0.x; bvv[1]=b0.y; bvv[2]=b0.z; bvv[3]=b0.w;
#pragma unroll
            for (int r = 0; r < 8; r++)
#pragma unroll
                for (int c = 0; c < 4; c++)
                    acc[r][c] = fmaf(avv[r], bvv[c], acc[r][c]);
        }
    }

    float* o = out + (size_t)NBS * ND + (size_t)which * NB * ND * ND
                 + (size_t)b * ND * ND + colh * 64;
#pragma unroll
    for (int r = 0; r < 8; r++) {
        float4 res = make_float4(acc[r][0], acc[r][1], acc[r][2], acc[r][3]);
        *(float4*)&o[(i0 + r) * ND + j0] = res;
    }
}

// ---------------------------------------------------------------------------
extern "C" void kernel_launch(void* const* d_in, const int* in_sizes, int n_in,
                              void* d_out, int out_size) {
    const float* x  = (const float*)d_in[0];
    const float* Wk = (const float*)d_in[1];
    const float* Wv = (const float*)d_in[2];
    const float* Wq = (const float*)d_in[3];
    const float* Wg = (const float*)d_in[4];
    const float* bg = (const float*)d_in[5];
    float* out = (float*)d_out;

    const int proj_smem = (64 * ND + 32 * ND * 4) * (int)sizeof(float); // 96KB
    cudaFuncSetAttribute(proj_gates_kernel,
                         cudaFuncAttributeMaxDynamicSharedMemorySize, proj_smem);

    proj_gates_kernel<<<dim3(128, 4), 256, proj_smem>>>(x, Wk, Wv, Wq, Wg, bg);
    bwd_p1_kernel<<<dim3(NCH + 1, NB), 128>>>();
    scan_p2<<<NB, 1024>>>();
    scan_p3<<<dim3(NCH, NB), 128>>>(out);
    final_kernel<<<dim3(2, 2, 8), 256>>>(out);
}